// round 4
// baseline (speedup 1.0000x reference)
#include <cuda_runtime.h>
#include <float.h>

#define CCH   512
#define HH    38
#define WW    63
#define HWN   (HH*WW)          /* 2394 */
#define NROI  1024
#define PRE   14               /* pre-pool grid 14x14 */
#define PS    7
#define TILE_STRIDE 513        /* 512 + 1 pad: conflict-free strided reads */
#define SMEM_BYTES  (49*TILE_STRIDE*4)   /* 100548 B */

// HWC-transposed feature map scratch (4.9 MB).
__device__ float g_hwc[HWN * CCH];

// ---------------------------------------------------------------------------
// Kernel 1: CHW -> HWC transpose (tiled, conflict-free)
// ---------------------------------------------------------------------------
__global__ void transpose_kernel(const float* __restrict__ src) {
    __shared__ float t[32][33];
    int hw0 = blockIdx.x * 32;
    int c0  = blockIdx.y * 32;

    int hw = hw0 + threadIdx.x;
#pragma unroll
    for (int dy = 0; dy < 32; dy += 8) {
        int c = c0 + threadIdx.y + dy;
        if (hw < HWN && c < CCH)
            t[threadIdx.y + dy][threadIdx.x] = src[c * HWN + hw];
    }
    __syncthreads();

    int c2 = c0 + threadIdx.x;
#pragma unroll
    for (int dy = 0; dy < 32; dy += 8) {
        int hh = hw0 + threadIdx.y + dy;
        if (hh < HWN && c2 < CCH)
            g_hwc[hh * CCH + c2] = t[threadIdx.x][threadIdx.y + dy];
    }
}

// ---------------------------------------------------------------------------
__device__ __forceinline__ float4 lerp4(float4 a, float4 b, float w) {
    float4 r;
    r.x = a.x + (b.x - a.x) * w;
    r.y = a.y + (b.y - a.y) * w;
    r.z = a.z + (b.z - a.z) * w;
    r.w = a.w + (b.w - a.w) * w;
    return r;
}
__device__ __forceinline__ float4 mask4(float4 v, bool valid) {
    float4 r;
    r.x = valid ? v.x : 0.f;
    r.y = valid ? v.y : 0.f;
    r.z = valid ? v.z : 0.f;
    r.w = valid ? v.w : 0.f;
    return r;
}
__device__ __forceinline__ float4 fmax4(float4 a, float4 b) {
    float4 r;
    r.x = fmaxf(a.x, b.x); r.y = fmaxf(a.y, b.y);
    r.z = fmaxf(a.z, b.z); r.w = fmaxf(a.w, b.w);
    return r;
}

// ---------------------------------------------------------------------------
// Kernel 2: per-roi crop-and-resize (bilinear 14x14) + 2x2 maxpool -> 7x7,
// with uniform-branch dedup of shared corner rows/columns inside each cell.
// Staging: tile[pos][c] stride 513 -> STS.128 conflict-free, flush scalar
// conflict-free (bank stride 1) + coalesced STG.
// ---------------------------------------------------------------------------
__global__ __launch_bounds__(512, 2)
void roi_kernel(const float* __restrict__ rois, float* __restrict__ out) {
    extern __shared__ float tile[];           // [49][TILE_STRIDE]

    // stage-1: per-sample
    __shared__ int   sy0[PRE], sy1[PRE], sx0[PRE], sx1[PRE];
    __shared__ float swy[PRE], swx[PRE];
    __shared__ unsigned svy[PRE], svx[PRE];
    // stage-2: per pooled cell (premultiplied offsets in float4 units)
    __shared__ int   yR0[PS], yR1[PS], yR2[PS], yR3[PS], yCs[PS];
    __shared__ float yWa[PS], yWb[PS];
    __shared__ unsigned yVa[PS], yVb[PS];
    __shared__ int   xC0[PS], xC1[PS], xC2[PS], xC3[PS], xCs[PS];
    __shared__ float xWa[PS], xWb[PS];
    __shared__ unsigned xVa[PS], xVb[PS];

    const int r   = blockIdx.x;
    const int tid = threadIdx.x;

    // --- stage 1: per-axis sample coords / weights / validity (ref math) ---
    if (tid < 2 * PRE) {
        bool isx = tid >= PRE;
        int  i   = isx ? tid - PRE : tid;
        float lo    = rois[5 * r + (isx ? 1 : 2)];
        float hi    = rois[5 * r + (isx ? 3 : 4)];
        float dimm1 = isx ? (float)(WW - 1) : (float)(HH - 1);
        float an = lo * 0.0625f / dimm1;
        float bn = hi * 0.0625f / dimm1;
        float t  = (float)i / 13.0f;
        float v  = (an + t * (bn - an)) * dimm1;
        float f  = floorf(v);
        int p0   = (int)f;
        int lim  = (int)dimm1;
        int q0   = min(max(p0, 0), lim);
        int q1   = min(max(p0 + 1, 0), lim);
        float w  = v - f;
        unsigned ok = (v >= 0.0f && v <= dimm1) ? 1u : 0u;
        if (isx) { sx0[i] = q0; sx1[i] = q1; swx[i] = w; svx[i] = ok; }
        else     { sy0[i] = q0; sy1[i] = q1; swy[i] = w; svy[i] = ok; }
    }
    __syncthreads();

    // --- stage 2: per pooled cell structure + dedup case codes ---
    if (tid < 2 * PS) {
        bool isx = tid >= PS;
        int  q   = isx ? tid - PS : tid;
        int  i = 2 * q, j = 2 * q + 1;
        if (!isx) {
            int R0 = sy0[i], R1 = sy1[i], R2 = sy0[j], R3 = sy1[j];
            yCs[q] = (R2 == R0) ? 0 : ((R2 == R1) ? 1 : 2);
            yR0[q] = R0 * (WW * 128); yR1[q] = R1 * (WW * 128);
            yR2[q] = R2 * (WW * 128); yR3[q] = R3 * (WW * 128);
            yWa[q] = swy[i]; yWb[q] = swy[j];
            yVa[q] = svy[i]; yVb[q] = svy[j];
        } else {
            int C0 = sx0[i], C1 = sx1[i], C2 = sx0[j], C3 = sx1[j];
            xCs[q] = (C2 == C0) ? 0 : ((C2 == C1) ? 1 : 2);
            xC0[q] = C0 * 128; xC1[q] = C1 * 128;
            xC2[q] = C2 * 128; xC3[q] = C3 * 128;
            xWa[q] = swx[i]; xWb[q] = swx[j];
            xVa[q] = svx[i]; xVb[q] = svx[j];
        }
    }
    __syncthreads();

    const int c4 = tid & 127;                           // float4 channel index
    const float4* __restrict__ base = (const float4*)g_hwc + c4;

    int pos = tid >> 7;      // 0..3
    int py  = 0;
    int px  = pos;
    while (pos < 49) {
        const int   c0 = xC0[px], c1 = xC1[px], c2 = xC2[px], c3 = xC3[px];
        const int   xcs = xCs[px];
        const float wxa = xWa[px], wxb = xWb[px];
        const int   r0 = yR0[py], r1 = yR1[py], r2 = yR2[py], r3 = yR3[py];
        const int   ycs = yCs[py];
        const float wya = yWa[py], wyb = yWb[py];
        const bool  vaa = (yVa[py] & xVa[px]) != 0;
        const bool  vab = (yVa[py] & xVb[px]) != 0;
        const bool  vba = (yVb[py] & xVa[px]) != 0;
        const bool  vbb = (yVb[py] & xVb[px]) != 0;

        // horizontal interp for one row, deduping shared columns (uniform branch)
        auto hx_row = [&](int roff, float4& ha, float4& hb) {
            if (xcs == 0) {             // 2 unique cols
                float4 g0 = base[roff + c0];
                float4 g1 = base[roff + c1];
                ha = lerp4(g0, g1, wxa);
                hb = lerp4(g0, g1, wxb);
            } else if (xcs == 1) {      // 3 unique cols
                float4 g0 = base[roff + c0];
                float4 g1 = base[roff + c1];
                float4 g3 = base[roff + c3];
                ha = lerp4(g0, g1, wxa);
                hb = lerp4(g1, g3, wxb);
            } else {                    // 4 unique cols
                float4 g0 = base[roff + c0];
                float4 g1 = base[roff + c1];
                float4 g2 = base[roff + c2];
                float4 g3 = base[roff + c3];
                ha = lerp4(g0, g1, wxa);
                hb = lerp4(g2, g3, wxb);
            }
        };

        float4 h0a, h0b, h1a, h1b;
        hx_row(r0, h0a, h0b);
        hx_row(r1, h1a, h1b);

        float4 h2a, h2b, h3a, h3b;
        if (ycs == 0) {                 // reuse both rows
            h2a = h0a; h2b = h0b; h3a = h1a; h3b = h1b;
        } else if (ycs == 1) {          // reuse one row
            h2a = h1a; h2b = h1b;
            hx_row(r3, h3a, h3b);
        } else {
            hx_row(r2, h2a, h2b);
            hx_row(r3, h3a, h3b);
        }

        float4 s00 = mask4(lerp4(h0a, h1a, wya), vaa);
        float4 s01 = mask4(lerp4(h0b, h1b, wya), vab);
        float4 s10 = mask4(lerp4(h2a, h3a, wyb), vba);
        float4 s11 = mask4(lerp4(h2b, h3b, wyb), vbb);
        float4 m = fmax4(fmax4(s00, s01), fmax4(s10, s11));

        // stage into shared: 4 consecutive words -> one STS.128, conflict-free
        float* row = tile + pos * TILE_STRIDE + c4 * 4;
        row[0] = m.x; row[1] = m.y; row[2] = m.z; row[3] = m.w;

        pos += 4;
        px  += 4;
        if (px >= 7) { px -= 7; ++py; }
    }
    __syncthreads();

    // --- flush: out[r][c][pos] = tile[pos][c]; stride-513 reads are
    //     bank-stride-1 (conflict-free), stores fully coalesced ---
    float* __restrict__ dst = out + (size_t)r * (CCH * 49);
    int c   = tid / 49;
    int pos2 = tid - c * 49;
    for (int j = tid; j < CCH * 49; j += 512) {
        dst[j] = tile[pos2 * TILE_STRIDE + c];
        pos2 += 22; c += 10;              // 512 = 10*49 + 22
        if (pos2 >= 49) { pos2 -= 49; ++c; }
    }
}

// ---------------------------------------------------------------------------
extern "C" void kernel_launch(void* const* d_in, const int* in_sizes, int n_in,
                              void* d_out, int out_size) {
    const float* bottom;
    const float* rois;
    if (n_in >= 2 && in_sizes[0] == 5 * NROI) {
        rois   = (const float*)d_in[0];
        bottom = (const float*)d_in[1];
    } else {
        bottom = (const float*)d_in[0];
        rois   = (const float*)d_in[1];
    }
    float* out = (float*)d_out;

    cudaFuncSetAttribute(roi_kernel,
                         cudaFuncAttributeMaxDynamicSharedMemorySize, SMEM_BYTES);

    dim3 tb(32, 8);
    dim3 tg((HWN + 31) / 32, (CCH + 31) / 32);
    transpose_kernel<<<tg, tb>>>(bottom);
    roi_kernel<<<NROI, 512, SMEM_BYTES>>>(rois, out);
}

// round 5
// speedup vs baseline: 1.3105x; 1.3105x over previous
#include <cuda_runtime.h>
#include <float.h>

#define CCH   512
#define HH    38
#define WW    63
#define HWN   (HH*WW)          /* 2394 */
#define NROI  1024
#define PRE   14               /* pre-pool grid 14x14 */
#define PS    7
#define TILE_STRIDE 513        /* 512 + 1 pad: conflict-free strided reads */
#define SMEM_BYTES  (49*TILE_STRIDE*4)   /* 100548 B */

// HWC-transposed feature map scratch (4.9 MB).
__device__ float g_hwc[HWN * CCH];

// ---------------------------------------------------------------------------
// Kernel 1: CHW -> HWC transpose (tiled, conflict-free)
// ---------------------------------------------------------------------------
__global__ void transpose_kernel(const float* __restrict__ src) {
    __shared__ float t[32][33];
    int hw0 = blockIdx.x * 32;
    int c0  = blockIdx.y * 32;

    int hw = hw0 + threadIdx.x;
#pragma unroll
    for (int dy = 0; dy < 32; dy += 8) {
        int c = c0 + threadIdx.y + dy;
        if (hw < HWN && c < CCH)
            t[threadIdx.y + dy][threadIdx.x] = src[c * HWN + hw];
    }
    __syncthreads();

    int c2 = c0 + threadIdx.x;
#pragma unroll
    for (int dy = 0; dy < 32; dy += 8) {
        int hh = hw0 + threadIdx.y + dy;
        if (hh < HWN && c2 < CCH)
            g_hwc[hh * CCH + c2] = t[threadIdx.x][threadIdx.y + dy];
    }
}

// ---------------------------------------------------------------------------
__device__ __forceinline__ float4 lerp4(float4 a, float4 b, float w) {
    float4 r;
    r.x = a.x + (b.x - a.x) * w;
    r.y = a.y + (b.y - a.y) * w;
    r.z = a.z + (b.z - a.z) * w;
    r.w = a.w + (b.w - a.w) * w;
    return r;
}
// running max with validity mask; applied IMMEDIATELY to keep live ranges short
__device__ __forceinline__ void max4(float4& m, float4 v, bool valid) {
    float x = valid ? v.x : 0.f;
    float y = valid ? v.y : 0.f;
    float z = valid ? v.z : 0.f;
    float w = valid ? v.w : 0.f;
    m.x = fmaxf(m.x, x); m.y = fmaxf(m.y, y);
    m.z = fmaxf(m.z, z); m.w = fmaxf(m.w, w);
}

// ---------------------------------------------------------------------------
// Kernel 2: per-roi crop-and-resize (bilinear 14x14) + 2x2 maxpool -> 7x7,
// with uniform-branch dedup of shared corner rows/columns inside each cell.
// ---------------------------------------------------------------------------
__global__ __launch_bounds__(512, 2)
void roi_kernel(const float* __restrict__ rois, float* __restrict__ out) {
    extern __shared__ float tile[];           // [49][TILE_STRIDE]

    // stage-1: per-sample
    __shared__ int   sy0[PRE], sy1[PRE], sx0[PRE], sx1[PRE];
    __shared__ float swy[PRE], swx[PRE];
    __shared__ unsigned svy[PRE], svx[PRE];
    // stage-2: per pooled cell (premultiplied offsets in float4 units)
    __shared__ int   yR0[PS], yR1[PS], yR2[PS], yR3[PS], yCs[PS];
    __shared__ float yWa[PS], yWb[PS];
    __shared__ unsigned yVa[PS], yVb[PS];
    __shared__ int   xC0[PS], xC1[PS], xC2[PS], xC3[PS], xCs[PS];
    __shared__ float xWa[PS], xWb[PS];
    __shared__ unsigned xVa[PS], xVb[PS];

    const int r   = blockIdx.x;
    const int tid = threadIdx.x;

    // --- stage 1: per-axis sample coords / weights / validity (ref math) ---
    if (tid < 2 * PRE) {
        bool isx = tid >= PRE;
        int  i   = isx ? tid - PRE : tid;
        float lo    = rois[5 * r + (isx ? 1 : 2)];
        float hi    = rois[5 * r + (isx ? 3 : 4)];
        float dimm1 = isx ? (float)(WW - 1) : (float)(HH - 1);
        float an = lo * 0.0625f / dimm1;
        float bn = hi * 0.0625f / dimm1;
        float t  = (float)i / 13.0f;
        float v  = (an + t * (bn - an)) * dimm1;
        float f  = floorf(v);
        int p0   = (int)f;
        int lim  = (int)dimm1;
        int q0   = min(max(p0, 0), lim);
        int q1   = min(max(p0 + 1, 0), lim);
        float w  = v - f;
        unsigned ok = (v >= 0.0f && v <= dimm1) ? 1u : 0u;
        if (isx) { sx0[i] = q0; sx1[i] = q1; swx[i] = w; svx[i] = ok; }
        else     { sy0[i] = q0; sy1[i] = q1; swy[i] = w; svy[i] = ok; }
    }
    __syncthreads();

    // --- stage 2: per pooled cell structure + dedup case codes ---
    if (tid < 2 * PS) {
        bool isx = tid >= PS;
        int  q   = isx ? tid - PS : tid;
        int  i = 2 * q, j = 2 * q + 1;
        if (!isx) {
            int R0 = sy0[i], R1 = sy1[i], R2 = sy0[j], R3 = sy1[j];
            yCs[q] = (R2 == R0) ? 0 : ((R2 == R1) ? 1 : 2);
            yR0[q] = R0 * (WW * 128); yR1[q] = R1 * (WW * 128);
            yR2[q] = R2 * (WW * 128); yR3[q] = R3 * (WW * 128);
            yWa[q] = swy[i]; yWb[q] = swy[j];
            yVa[q] = svy[i]; yVb[q] = svy[j];
        } else {
            int C0 = sx0[i], C1 = sx1[i], C2 = sx0[j], C3 = sx1[j];
            xCs[q] = (C2 == C0) ? 0 : ((C2 == C1) ? 1 : 2);
            xC0[q] = C0 * 128; xC1[q] = C1 * 128;
            xC2[q] = C2 * 128; xC3[q] = C3 * 128;
            xWa[q] = swx[i]; xWb[q] = swx[j];
            xVa[q] = svx[i]; xVb[q] = svx[j];
        }
    }
    __syncthreads();

    const int c4 = tid & 127;                           // float4 channel index
    const float4* __restrict__ base = (const float4*)g_hwc + c4;

    int pos = tid >> 7;      // 0..3
    int py  = 0;
    int px  = pos;
    while (pos < 49) {
        const int   c0 = xC0[px], c1 = xC1[px], c2 = xC2[px], c3 = xC3[px];
        const int   xcs = xCs[px];
        const float wxa = xWa[px], wxb = xWb[px];
        const int   r0 = yR0[py], r1 = yR1[py], r2 = yR2[py], r3 = yR3[py];
        const int   ycs = yCs[py];
        const float wya = yWa[py], wyb = yWb[py];
        const bool  vaa = (yVa[py] & xVa[px]) != 0;
        const bool  vab = (yVa[py] & xVb[px]) != 0;
        const bool  vba = (yVb[py] & xVa[px]) != 0;
        const bool  vbb = (yVb[py] & xVb[px]) != 0;

        // horizontal interp for one row, deduping shared columns (uniform branch)
        auto hx_row = [&](int roff, float4& ha, float4& hb) {
            if (xcs == 0) {             // 2 unique cols
                float4 g0 = base[roff + c0];
                float4 g1 = base[roff + c1];
                ha = lerp4(g0, g1, wxa);
                hb = lerp4(g0, g1, wxb);
            } else if (xcs == 1) {      // 3 unique cols
                float4 g0 = base[roff + c0];
                float4 g1 = base[roff + c1];
                float4 g3 = base[roff + c3];
                ha = lerp4(g0, g1, wxa);
                hb = lerp4(g1, g3, wxb);
            } else {                    // 4 unique cols
                float4 g0 = base[roff + c0];
                float4 g1 = base[roff + c1];
                float4 g2 = base[roff + c2];
                float4 g3 = base[roff + c3];
                ha = lerp4(g0, g1, wxa);
                hb = lerp4(g2, g3, wxb);
            }
        };

        float4 m = make_float4(-FLT_MAX, -FLT_MAX, -FLT_MAX, -FLT_MAX);

        float4 h0a, h0b, h1a, h1b;
        hx_row(r0, h0a, h0b);
        hx_row(r1, h1a, h1b);
        max4(m, lerp4(h0a, h1a, wya), vaa);
        max4(m, lerp4(h0b, h1b, wya), vab);

        float4 h2a, h2b, h3a, h3b;
        if (ycs == 0) {                 // reuse both rows
            h2a = h0a; h2b = h0b; h3a = h1a; h3b = h1b;
        } else if (ycs == 1) {          // reuse one row
            h2a = h1a; h2b = h1b;
            hx_row(r3, h3a, h3b);
        } else {
            hx_row(r2, h2a, h2b);
            hx_row(r3, h3a, h3b);
        }
        max4(m, lerp4(h2a, h3a, wyb), vba);
        max4(m, lerp4(h2b, h3b, wyb), vbb);

        // stage into shared: 4 consecutive words -> one STS.128, conflict-free
        float* row = tile + pos * TILE_STRIDE + c4 * 4;
        row[0] = m.x; row[1] = m.y; row[2] = m.z; row[3] = m.w;

        pos += 4;
        px  += 4;
        if (px >= 7) { px -= 7; ++py; }
    }
    __syncthreads();

    // --- flush: out[r][c][pos] = tile[pos][c]; conflict-free + coalesced ---
    float* __restrict__ dst = out + (size_t)r * (CCH * 49);
    int c    = tid / 49;
    int pos2 = tid - c * 49;
    for (int j = tid; j < CCH * 49; j += 512) {
        dst[j] = tile[pos2 * TILE_STRIDE + c];
        pos2 += 22; c += 10;              // 512 = 10*49 + 22
        if (pos2 >= 49) { pos2 -= 49; ++c; }
    }
}

// ---------------------------------------------------------------------------
extern "C" void kernel_launch(void* const* d_in, const int* in_sizes, int n_in,
                              void* d_out, int out_size) {
    const float* bottom;
    const float* rois;
    if (n_in >= 2 && in_sizes[0] == 5 * NROI) {
        rois   = (const float*)d_in[0];
        bottom = (const float*)d_in[1];
    } else {
        bottom = (const float*)d_in[0];
        rois   = (const float*)d_in[1];
    }
    float* out = (float*)d_out;

    cudaFuncSetAttribute(roi_kernel,
                         cudaFuncAttributeMaxDynamicSharedMemorySize, SMEM_BYTES);

    dim3 tb(32, 8);
    dim3 tg((HWN + 31) / 32, (CCH + 31) / 32);
    transpose_kernel<<<tg, tb>>>(bottom);
    roi_kernel<<<NROI, 512, SMEM_BYTES>>>(rois, out);
}